// round 2
// baseline (speedup 1.0000x reference)
#include <cuda_runtime.h>
#include <cstdint>

constexpr int GRID  = 1184;   // 148 SMs * 8 blocks -> exactly one wave at 256 thr/blk
constexpr int BLOCK = 256;

// Per-block partial sums of squares. Fully overwritten every replay by
// reduce_sumsq_kernel (no zeroing needed -> no zero kernel).
__device__ float g_partials[GRID];

struct TensorSet {
    const float4* p[5];
    float4*       o[5];   // output slice base (concatenated layout), vec4 units
    long          n[5];   // vec4 element counts
};

__device__ __forceinline__ float dot4_acc(float4 v, float a) {
    a = fmaf(v.x, v.x, a);
    a = fmaf(v.y, v.y, a);
    a = fmaf(v.z, v.z, a);
    a = fmaf(v.w, v.w, a);
    return a;
}

// Pass 1: sum of squares -> per-block partials. Forward iteration order so the
// tail of the last tensor ends up resident in L2 for pass 2.
__global__ void __launch_bounds__(BLOCK) reduce_sumsq_kernel(TensorSet ts) {
    const long stride = (long)GRID * BLOCK;
    const long base   = (long)blockIdx.x * BLOCK + threadIdx.x;

    float a0 = 0.f, a1 = 0.f, a2 = 0.f, a3 = 0.f;

    #pragma unroll
    for (int t = 0; t < 5; ++t) {
        const float4* __restrict__ p = ts.p[t];
        const long n = ts.n[t];
        long i = base;
        for (; i + 3 * stride < n; i += 4 * stride) {
            float4 v0 = p[i];
            float4 v1 = p[i + stride];
            float4 v2 = p[i + 2 * stride];
            float4 v3 = p[i + 3 * stride];
            a0 = dot4_acc(v0, a0);
            a1 = dot4_acc(v1, a1);
            a2 = dot4_acc(v2, a2);
            a3 = dot4_acc(v3, a3);
        }
        for (; i < n; i += stride)
            a0 = dot4_acc(p[i], a0);
    }

    float acc = (a0 + a1) + (a2 + a3);

    #pragma unroll
    for (int off = 16; off > 0; off >>= 1)
        acc += __shfl_xor_sync(0xFFFFFFFFu, acc, off);

    __shared__ float warp_sums[BLOCK / 32];
    const int lane = threadIdx.x & 31;
    const int wid  = threadIdx.x >> 5;
    if (lane == 0) warp_sums[wid] = acc;
    __syncthreads();

    if (wid == 0) {
        float s = (lane < (BLOCK >> 5)) ? warp_sums[lane] : 0.0f;
        #pragma unroll
        for (int off = 4; off > 0; off >>= 1)
            s += __shfl_xor_sync(0xFFFFFFFFu, s, off);
        if (lane == 0)
            g_partials[blockIdx.x] = s;
    }
}

// Pass 2: every block redundantly reduces the partials (deterministic, same
// fixed order per block -> bitwise-identical scale across blocks), then streams
// tensors in REVERSE order, indices DESCENDING, to hit the L2-resident tail
// left by pass 1. __ldcs/__stcs = evict-first, keeps that residue alive.
__global__ void __launch_bounds__(BLOCK) scale_kernel(TensorSet ts) {
    // --- reduce partials in double (precision + determinism) ---
    double d = 0.0;
    for (int i = threadIdx.x; i < GRID; i += BLOCK)
        d += (double)g_partials[i];

    #pragma unroll
    for (int off = 16; off > 0; off >>= 1)
        d += __shfl_xor_sync(0xFFFFFFFFu, d, off);

    __shared__ double warp_sums_d[BLOCK / 32];
    __shared__ float  s_scale;
    const int lane = threadIdx.x & 31;
    const int wid  = threadIdx.x >> 5;
    if (lane == 0) warp_sums_d[wid] = d;
    __syncthreads();
    if (wid == 0) {
        double s = (lane < (BLOCK >> 5)) ? warp_sums_d[lane] : 0.0;
        #pragma unroll
        for (int off = 4; off > 0; off >>= 1)
            s += __shfl_xor_sync(0xFFFFFFFFu, s, off);
        if (lane == 0) {
            float norm = sqrtf((float)s);
            s_scale = (norm > 1.0f) ? (1.0f / (norm + 1e-6f)) : 1.0f;
        }
    }
    __syncthreads();
    const float scale = s_scale;

    // --- streaming scale, reversed traversal ---
    const long stride = (long)GRID * BLOCK;
    const long base   = (long)blockIdx.x * BLOCK + threadIdx.x;

    #pragma unroll
    for (int t = 4; t >= 0; --t) {
        const float4* __restrict__ p = ts.p[t];
        float4* __restrict__ o = ts.o[t];
        const long n = ts.n[t];
        long k = base;
        for (; k + 3 * stride < n; k += 4 * stride) {
            const long i0 = n - 1 - k;
            const long i1 = i0 - stride;
            const long i2 = i0 - 2 * stride;
            const long i3 = i0 - 3 * stride;
            float4 v0 = __ldcs(p + i0);
            float4 v1 = __ldcs(p + i1);
            float4 v2 = __ldcs(p + i2);
            float4 v3 = __ldcs(p + i3);
            v0.x *= scale; v0.y *= scale; v0.z *= scale; v0.w *= scale;
            v1.x *= scale; v1.y *= scale; v1.z *= scale; v1.w *= scale;
            v2.x *= scale; v2.y *= scale; v2.z *= scale; v2.w *= scale;
            v3.x *= scale; v3.y *= scale; v3.z *= scale; v3.w *= scale;
            __stcs(o + i0, v0);
            __stcs(o + i1, v1);
            __stcs(o + i2, v2);
            __stcs(o + i3, v3);
        }
        for (; k < n; k += stride) {
            const long i = n - 1 - k;
            float4 v = __ldcs(p + i);
            v.x *= scale; v.y *= scale; v.z *= scale; v.w *= scale;
            __stcs(o + i, v);
        }
    }
}

extern "C" void kernel_launch(void* const* d_in, const int* in_sizes, int n_in,
                              void* d_out, int out_size) {
    TensorSet ts;
    long off = 0;
    float* out = (float*)d_out;
    for (int t = 0; t < 5; ++t) {
        ts.p[t] = (const float4*)d_in[t];
        ts.o[t] = (float4*)(out + off);
        ts.n[t] = (long)in_sizes[t] / 4;   // all counts divisible by 4
        off += (long)in_sizes[t];
    }

    reduce_sumsq_kernel<<<GRID, BLOCK>>>(ts);
    scale_kernel<<<GRID, BLOCK>>>(ts);
}